// round 16
// baseline (speedup 1.0000x reference)
#include <cuda_runtime.h>
#include <cuda_fp16.h>
#include <math.h>
#include <stdint.h>

#define TOK   2048
#define HD    512
#define FD    2048
#define NE    8
#define NSLOTS (TOK*2)

// ---------------- device scratch ----------------
__device__ int   g_count[NE];
__device__ int   g_base[NE];
__device__ int   g_cursor[NE];
__device__ int   g_topi[TOK*2];
__device__ float g_topw[TOK*2];
__device__ int   g_perm[NSLOTS];
__device__ float g_wt[NSLOTS];
__device__ int   g_slot_of[TOK*2];
__device__ __align__(16) __half gx16  [(size_t)TOK*HD];     // fp16(x)
__device__ __align__(16) __half gact16[(size_t)NSLOTS*FD];  // fp16(silu(h))
__device__ __align__(16) __half gw1   [(size_t)NE*FD*HD];   // [E][F][H] fp16(W1^T)
__device__ __align__(16) __half gw2   [(size_t)NE*HD*FD];   // [E][H][F] fp16(W2^T)
__device__ __align__(16) float  gyy   [(size_t)NSLOTS*HD];

// ---------------- PTX helpers (sm_80-portable only) ----------------
__device__ __forceinline__ uint32_t smaddr(const void* p) {
    uint32_t a;
    asm("{ .reg .u64 t; cvta.to.shared.u64 t, %1; cvt.u32.u64 %0, t; }" : "=r"(a) : "l"(p));
    return a;
}
__device__ __forceinline__ void ldmx4(uint32_t* r, uint32_t addr) {
    asm volatile("ldmatrix.sync.aligned.m8n8.x4.shared.b16 {%0,%1,%2,%3}, [%4];"
        : "=r"(r[0]), "=r"(r[1]), "=r"(r[2]), "=r"(r[3]) : "r"(addr));
}
// fp16-accumulator MMA, D/C in-out (chained)
__device__ __forceinline__ void hmma16(uint32_t* d, const uint32_t* a, const uint32_t* b) {
    asm volatile("mma.sync.aligned.m16n8k16.row.col.f16.f16.f16.f16 "
        "{%0,%1}, {%2,%3,%4,%5}, {%6,%7}, {%0,%1};"
        : "+r"(d[0]), "+r"(d[1])
        : "r"(a[0]), "r"(a[1]), "r"(a[2]), "r"(a[3]), "r"(b[0]), "r"(b[1]));
}
__device__ __forceinline__ void cp16(uint32_t dst, const void* src) {
    asm volatile("cp.async.cg.shared.global [%0], [%1], 16;" :: "r"(dst), "l"(src));
}
#define CPC() asm volatile("cp.async.commit_group;" ::: "memory")
template<int N> __device__ __forceinline__ void cpw() {
    asm volatile("cp.async.wait_group %0;" :: "n"(N) : "memory");
}

// pack 8 fp32 -> 8 fp16 (uint4)
__device__ __forceinline__ void h8pack(const float* f, uint4& o) {
    uint32_t h[8];
#pragma unroll
    for (int i = 0; i < 8; i++)
        h[i] = (uint32_t)__half_as_ushort(__float2half_rn(f[i]));
    o.x = h[0] | (h[1] << 16); o.y = h[2] | (h[3] << 16);
    o.z = h[4] | (h[5] << 16); o.w = h[6] | (h[7] << 16);
}

// ---------------- pre-pass: W [e][K][N] fp32 -> [e][N][K] fp16 ----------------
template<int K, int N, bool W1SEL>
__global__ void w_transpose_kernel(const float* __restrict__ W) {
    __shared__ float sm[32][65];                   // [n][k]
    __half* T = W1SEL ? gw1 : gw2;
    int e  = blockIdx.z;
    int n0 = blockIdx.x * 32, k0 = blockIdx.y * 64;
    int tx = threadIdx.x, ty = threadIdx.y;
    const float* Wp = W + (size_t)e * K * N;
#pragma unroll
    for (int j = 0; j < 8; j++)
        sm[tx][ty * 8 + j] = Wp[(size_t)(k0 + ty * 8 + j) * N + n0 + tx];
    __syncthreads();
    int t  = ty * 32 + tx;
    int n  = t >> 3;
    int ko = (t & 7) * 8;
    float f[8];
#pragma unroll
    for (int i = 0; i < 8; i++) f[i] = sm[n][ko + i];
    uint4 o; h8pack(f, o);
    *(uint4*)(T + ((size_t)e * N + n0 + n) * K + k0 + ko) = o;
}

// ---------------- routing (fused: also emits fp16 x) ----------------
__global__ void init_kernel() {
    int i = threadIdx.x;
    if (i < NE) { g_count[i] = 0; g_cursor[i] = 0; }
}

__global__ void router_cvt_kernel(const float* __restrict__ x,
                                  const float* __restrict__ Wg) {
    int warp = threadIdx.x >> 5, lane = threadIdx.x & 31;
    int t = blockIdx.x * 8 + warp;
    if (t >= TOK) return;
    float acc[NE];
#pragma unroll
    for (int e = 0; e < NE; e++) acc[e] = 0.f;
    const float4* xr = (const float4*)(x + (size_t)t * HD);
#pragma unroll
    for (int it = 0; it < HD/128; it++) {
        int i = it * 32 + lane;
        float4 xv = xr[i];
        uint2 pk;
        pk.x = (uint32_t)__half_as_ushort(__float2half_rn(xv.x))
             | ((uint32_t)__half_as_ushort(__float2half_rn(xv.y)) << 16);
        pk.y = (uint32_t)__half_as_ushort(__float2half_rn(xv.z))
             | ((uint32_t)__half_as_ushort(__float2half_rn(xv.w)) << 16);
        *(uint2*)(gx16 + (size_t)t * HD + i * 4) = pk;
#pragma unroll
        for (int e = 0; e < NE; e++) {
            float4 w = ((const float4*)(Wg + e*HD))[i];
            acc[e] += xv.x*w.x + xv.y*w.y + xv.z*w.z + xv.w*w.w;
        }
    }
#pragma unroll
    for (int off = 16; off > 0; off >>= 1)
#pragma unroll
        for (int e = 0; e < NE; e++)
            acc[e] += __shfl_xor_sync(0xffffffffu, acc[e], off);
    if (lane == 0) {
        int i0 = 0;
#pragma unroll
        for (int e = 1; e < NE; e++) if (acc[e] > acc[i0]) i0 = e;
        int i1 = (i0 == 0) ? 1 : 0;
#pragma unroll
        for (int e = 0; e < NE; e++)
            if (e != i0 && acc[e] > acc[i1]) i1 = e;
        float e1 = expf(acc[i1] - acc[i0]);
        float inv = 1.f / (1.f + e1);
        g_topi[t*2+0] = i0; g_topw[t*2+0] = inv;
        g_topi[t*2+1] = i1; g_topw[t*2+1] = e1 * inv;
        atomicAdd(&g_count[i0], 1);
        atomicAdd(&g_count[i1], 1);
    }
}

__global__ void scan_kernel() {
    int s = 0;
#pragma unroll
    for (int e = 0; e < NE; e++) { g_base[e] = s; s += g_count[e]; }
}

__global__ void scatter_kernel() {
    int t = blockIdx.x * 256 + threadIdx.x;
    if (t >= TOK) return;
#pragma unroll
    for (int k = 0; k < 2; k++) {
        int e = g_topi[t*2+k];
        int pos = atomicAdd(&g_cursor[e], 1);
        int slot = g_base[e] + pos;
        g_perm[slot] = t;
        g_wt[slot]   = g_topw[t*2+k];
        g_slot_of[t*2+k] = slot;
    }
}

// ---------------- grouped GEMM: fp16-accum MMA pairs + fp32 master accums ----------------
// Layout/pipeline byte-identical to the passing R15 build (4 stages x 8KB, 32B
// rows, swizzle h ^ ((row>>2)&1), paired chunks, one barrier per K32).
// NEW: per K32 pair each tile runs 2 chained f16-accumulator MMAs (rt ~2x the
// f32-accum form), then spills once into fp32 master accumulators.
#define PLB   4096            // bytes per plane (128 rows x 32B)
#define STGB  (2*PLB)         // bytes per stage

template<int KDIM, int NDIM, bool PASS1>
__global__ __launch_bounds__(256, 2)
void moe_gemm_h16(const float* __restrict__ bias) {
    __shared__ __align__(16) char smem[4*STGB];   // 32768 B static

    int e   = blockIdx.z;
    int cnt = g_count[e];
    int m0  = blockIdx.y * 128;
    if (m0 >= cnt) return;
    int n0   = blockIdx.x * 128;
    int base = g_base[e];

    int tid = threadIdx.x, wid = tid >> 5, lane = tid & 31;
    int wm = wid & 3, wn = wid >> 2;
    uint32_t smb = smaddr(smem);

    const __half* A_g = PASS1 ? gx16 : gact16;
    const __half* B_g = PASS1 ? gw1  : gw2;

    // loader: plane p = tid>>7 (0=A,1=B), row r = tid&127, 32B per chunk
    int p = tid >> 7, r = tid & 127;
    const char* src;
    if (p == 0) {
        int mr = m0 + r; if (mr >= cnt) mr = cnt - 1;
        int ar = PASS1 ? g_perm[base + mr] : (base + mr);
        src = (const char*)(A_g + (size_t)ar * KDIM);
    } else {
        src = (const char*)(B_g + ((size_t)e * NDIM + n0 + r) * KDIM);
    }
    int s = (r >> 2) & 1;
    uint32_t d0 = (uint32_t)(p*PLB + r*32 + s*16);
    uint32_t d1 = (uint32_t)(p*PLB + r*32 + (s^1)*16);

    float acc[2][8][4];
#pragma unroll
    for (int a = 0; a < 2; a++)
#pragma unroll
        for (int b = 0; b < 8; b++)
#pragma unroll
            for (int c = 0; c < 4; c++) acc[a][b][c] = 0.f;

    // ldmatrix lane addressing (fragment mapping proven R3..R15)
    const int a_r = lane & 15, ac = lane >> 4;
    const int b_n = ((lane >> 4) & 1) * 8 + (lane & 7);
    const int bc  = (lane >> 3) & 1;

    const int NCH = KDIM / 16;   // 32 or 128 (even)

    // prologue: chunks 0,1 into stages 0,1
    {
        cp16(smb + 0*STGB + d0, src);        cp16(smb + 0*STGB + d1, src + 16);
        cp16(smb + 1*STGB + d0, src + 32);   cp16(smb + 1*STGB + d1, src + 48);
        CPC();
    }

    for (int ci = 0; ci < NCH; ci += 2) {
        cpw<0>();
        __syncthreads();
        if (ci + 2 < NCH) {
            uint32_t sgA = smb + ((ci + 2) & 3) * STGB;
            uint32_t sgB = smb + ((ci + 3) & 3) * STGB;
            uint32_t go  = (uint32_t)(ci + 2) * 32;
            cp16(sgA + d0, src + go);       cp16(sgA + d1, src + go + 16);
            cp16(sgB + d0, src + go + 32);  cp16(sgB + d1, src + go + 48);
            CPC();
        }

        // A fragments for both chunks of the pair
        uint32_t ah[2][2][4];
#pragma unroll
        for (int j = 0; j < 2; j++) {
            uint32_t sb = smb + ((ci + j) & 3) * STGB;
#pragma unroll
            for (int mt = 0; mt < 2; mt++) {
                int row = wm*32 + mt*16 + a_r;
                uint32_t co = (uint32_t)((ac ^ ((row >> 2) & 1)) * 16);
                ldmx4(ah[j][mt], sb + row*32 + co);
            }
        }

#pragma unroll
        for (int p4 = 0; p4 < 4; p4++) {
            uint32_t bh[2][4];
#pragma unroll
            for (int j = 0; j < 2; j++) {
                uint32_t sb = smb + ((ci + j) & 3) * STGB;
                int row = wn*64 + p4*16 + b_n;
                uint32_t co = (uint32_t)((bc ^ ((row >> 2) & 1)) * 16);
                ldmx4(bh[j], sb + PLB + row*32 + co);
            }
#pragma unroll
            for (int mt = 0; mt < 2; mt++) {
#pragma unroll
                for (int q = 0; q < 2; q++) {
                    uint32_t dt[2] = {0u, 0u};          // fp16 accumulator pair
                    hmma16(dt, ah[0][mt], &bh[0][q*2]);
                    hmma16(dt, ah[1][mt], &bh[1][q*2]);
                    float2 f0 = __half22float2(*(const __half2*)&dt[0]);
                    float2 f1 = __half22float2(*(const __half2*)&dt[1]);
                    float* a4 = acc[mt][p4*2 + q];
                    a4[0] += f0.x; a4[1] += f0.y;
                    a4[2] += f1.x; a4[3] += f1.y;
                }
            }
        }
    }

    // epilogue
    int rbase = wm*32 + (lane >> 2);
    int cbase = n0 + wn*64 + (lane & 3)*2;
#pragma unroll
    for (int mt = 0; mt < 2; mt++) {
#pragma unroll
        for (int sub = 0; sub < 2; sub++) {
            int m = m0 + rbase + mt*16 + sub*8;
            if (m >= cnt) continue;
            int slot = base + m;
            float wtv = PASS1 ? 1.f : g_wt[slot];
#pragma unroll
            for (int nt = 0; nt < 8; nt++) {
                int n = cbase + nt*8;
                float v0 = acc[mt][nt][sub*2+0] + __ldg(&bias[e*NDIM + n]);
                float v1 = acc[mt][nt][sub*2+1] + __ldg(&bias[e*NDIM + n + 1]);
                if (PASS1) {
                    v0 = v0 / (1.f + __expf(-v0));
                    v1 = v1 / (1.f + __expf(-v1));
                    uint32_t pk = (uint32_t)__half_as_ushort(__float2half_rn(v0))
                                | ((uint32_t)__half_as_ushort(__float2half_rn(v1)) << 16);
                    *(uint32_t*)(gact16 + (size_t)slot * NDIM + n) = pk;
                } else {
                    float2 o; o.x = v0 * wtv; o.y = v1 * wtv;
                    *(float2*)(gyy + (size_t)slot * NDIM + n) = o;
                }
            }
        }
    }
}

// ---------------- combine ----------------
__global__ void combine_kernel(float* __restrict__ out) {
    int idx = blockIdx.x * 256 + threadIdx.x;
    if (idx >= TOK * (HD/4)) return;
    int t  = idx / (HD/4);
    int h4 = idx % (HD/4);
    int s0 = g_slot_of[t*2+0];
    int s1 = g_slot_of[t*2+1];
    float4 a = *(const float4*)&gyy[(size_t)s0 * HD + h4*4];
    float4 b = *(const float4*)&gyy[(size_t)s1 * HD + h4*4];
    float4 o;
    o.x = a.x + b.x; o.y = a.y + b.y; o.z = a.z + b.z; o.w = a.w + b.w;
    *(float4*)&out[(size_t)t * HD + h4*4] = o;
}

// ---------------- launch ----------------
extern "C" void kernel_launch(void* const* d_in, const int* in_sizes, int n_in,
                              void* d_out, int out_size) {
    const float* x  = (const float*)d_in[0];
    const float* Wg = (const float*)d_in[1];
    const float* W1 = (const float*)d_in[2];  // [8][512][2048]
    const float* b1 = (const float*)d_in[3];
    const float* W2 = (const float*)d_in[4];  // [8][2048][512]
    const float* b2 = (const float*)d_in[5];
    float* out = (float*)d_out;

    init_kernel<<<1, 32>>>();
    w_transpose_kernel<HD, FD, true ><<<dim3(FD/32, HD/64, NE), dim3(32, 8)>>>(W1);
    w_transpose_kernel<FD, HD, false><<<dim3(HD/32, FD/64, NE), dim3(32, 8)>>>(W2);
    router_cvt_kernel<<<TOK/8, 256>>>(x, Wg);
    scan_kernel<<<1, 1>>>();
    scatter_kernel<<<TOK/256, 256>>>();

    // Pass A: gather(fp16 x) @ W1T -> silu -> gact16  (cnt_e <= 2048 -> <=16 m-tiles)
    moe_gemm_h16<HD, FD, true><<<dim3(FD/128, 16, NE), 256>>>(b1);
    // Pass B: gact16 @ W2T -> *wt -> gyy
    moe_gemm_h16<FD, HD, false><<<dim3(HD/128, 16, NE), 256>>>(b2);

    combine_kernel<<<(TOK*(HD/4) + 255)/256, 256>>>(out);
}

// round 17
// speedup vs baseline: 1.2292x; 1.2292x over previous
#include <cuda_runtime.h>
#include <cuda_fp16.h>
#include <math.h>
#include <stdint.h>

#define TOK   2048
#define HD    512
#define FD    2048
#define NE    8
#define NSLOTS (TOK*2)

// ---------------- device scratch ----------------
__device__ int   g_count[NE];
__device__ int   g_base[NE];
__device__ int   g_cursor[NE];
__device__ int   g_topi[TOK*2];
__device__ float g_topw[TOK*2];
__device__ int   g_perm[NSLOTS];
__device__ float g_wt[NSLOTS];
__device__ int   g_slot_of[TOK*2];
__device__ __align__(16) __half gx16  [(size_t)TOK*HD];     // fp16(x)
__device__ __align__(16) __half gact16[(size_t)NSLOTS*FD];  // fp16(silu(h))
__device__ __align__(16) __half gw1   [(size_t)NE*FD*HD];   // [E][F][H] fp16(W1^T)
__device__ __align__(16) __half gw2   [(size_t)NE*HD*FD];   // [E][H][F] fp16(W2^T)
__device__ __align__(16) float  gyy   [(size_t)NSLOTS*HD];

// ---------------- PTX helpers (sm_80-portable only) ----------------
__device__ __forceinline__ uint32_t smaddr(const void* p) {
    uint32_t a;
    asm("{ .reg .u64 t; cvta.to.shared.u64 t, %1; cvt.u32.u64 %0, t; }" : "=r"(a) : "l"(p));
    return a;
}
__device__ __forceinline__ void ldmx4(uint32_t* r, uint32_t addr) {
    asm volatile("ldmatrix.sync.aligned.m8n8.x4.shared.b16 {%0,%1,%2,%3}, [%4];"
        : "=r"(r[0]), "=r"(r[1]), "=r"(r[2]), "=r"(r[3]) : "r"(addr));
}
__device__ __forceinline__ void hmma(float* c, const uint32_t* a, const uint32_t* b) {
    asm volatile("mma.sync.aligned.m16n8k16.row.col.f32.f16.f16.f32 "
        "{%0,%1,%2,%3}, {%4,%5,%6,%7}, {%8,%9}, {%0,%1,%2,%3};"
        : "+f"(c[0]), "+f"(c[1]), "+f"(c[2]), "+f"(c[3])
        : "r"(a[0]), "r"(a[1]), "r"(a[2]), "r"(a[3]), "r"(b[0]), "r"(b[1]));
}
__device__ __forceinline__ void cp16(uint32_t dst, const void* src) {
    asm volatile("cp.async.cg.shared.global [%0], [%1], 16;" :: "r"(dst), "l"(src));
}
#define CPC() asm volatile("cp.async.commit_group;" ::: "memory")
template<int N> __device__ __forceinline__ void cpw() {
    asm volatile("cp.async.wait_group %0;" :: "n"(N) : "memory");
}

// pack 8 fp32 -> 8 fp16 (uint4)
__device__ __forceinline__ void h8pack(const float* f, uint4& o) {
    uint32_t h[8];
#pragma unroll
    for (int i = 0; i < 8; i++)
        h[i] = (uint32_t)__half_as_ushort(__float2half_rn(f[i]));
    o.x = h[0] | (h[1] << 16); o.y = h[2] | (h[3] << 16);
    o.z = h[4] | (h[5] << 16); o.w = h[6] | (h[7] << 16);
}

// ---------------- pre-pass: W [e][K][N] fp32 -> [e][N][K] fp16 ----------------
template<int K, int N, bool W1SEL>
__global__ void w_transpose_kernel(const float* __restrict__ W) {
    __shared__ float sm[32][65];                   // [n][k]
    __half* T = W1SEL ? gw1 : gw2;
    int e  = blockIdx.z;
    int n0 = blockIdx.x * 32, k0 = blockIdx.y * 64;
    int tx = threadIdx.x, ty = threadIdx.y;
    const float* Wp = W + (size_t)e * K * N;
#pragma unroll
    for (int j = 0; j < 8; j++)
        sm[tx][ty * 8 + j] = Wp[(size_t)(k0 + ty * 8 + j) * N + n0 + tx];
    __syncthreads();
    int t  = ty * 32 + tx;
    int n  = t >> 3;
    int ko = (t & 7) * 8;
    float f[8];
#pragma unroll
    for (int i = 0; i < 8; i++) f[i] = sm[n][ko + i];
    uint4 o; h8pack(f, o);
    *(uint4*)(T + ((size_t)e * N + n0 + n) * K + k0 + ko) = o;
}

// ---------------- routing (fused: also emits fp16 x) ----------------
__global__ void init_kernel() {
    int i = threadIdx.x;
    if (i < NE) { g_count[i] = 0; g_cursor[i] = 0; }
}

__global__ void router_cvt_kernel(const float* __restrict__ x,
                                  const float* __restrict__ Wg) {
    int warp = threadIdx.x >> 5, lane = threadIdx.x & 31;
    int t = blockIdx.x * 8 + warp;
    if (t >= TOK) return;
    float acc[NE];
#pragma unroll
    for (int e = 0; e < NE; e++) acc[e] = 0.f;
    const float4* xr = (const float4*)(x + (size_t)t * HD);
#pragma unroll
    for (int it = 0; it < HD/128; it++) {
        int i = it * 32 + lane;
        float4 xv = xr[i];
        uint2 pk;
        pk.x = (uint32_t)__half_as_ushort(__float2half_rn(xv.x))
             | ((uint32_t)__half_as_ushort(__float2half_rn(xv.y)) << 16);
        pk.y = (uint32_t)__half_as_ushort(__float2half_rn(xv.z))
             | ((uint32_t)__half_as_ushort(__float2half_rn(xv.w)) << 16);
        *(uint2*)(gx16 + (size_t)t * HD + i * 4) = pk;
#pragma unroll
        for (int e = 0; e < NE; e++) {
            float4 w = ((const float4*)(Wg + e*HD))[i];
            acc[e] += xv.x*w.x + xv.y*w.y + xv.z*w.z + xv.w*w.w;
        }
    }
#pragma unroll
    for (int off = 16; off > 0; off >>= 1)
#pragma unroll
        for (int e = 0; e < NE; e++)
            acc[e] += __shfl_xor_sync(0xffffffffu, acc[e], off);
    if (lane == 0) {
        int i0 = 0;
#pragma unroll
        for (int e = 1; e < NE; e++) if (acc[e] > acc[i0]) i0 = e;
        int i1 = (i0 == 0) ? 1 : 0;
#pragma unroll
        for (int e = 0; e < NE; e++)
            if (e != i0 && acc[e] > acc[i1]) i1 = e;
        float e1 = expf(acc[i1] - acc[i0]);
        float inv = 1.f / (1.f + e1);
        g_topi[t*2+0] = i0; g_topw[t*2+0] = inv;
        g_topi[t*2+1] = i1; g_topw[t*2+1] = e1 * inv;
        atomicAdd(&g_count[i0], 1);
        atomicAdd(&g_count[i1], 1);
    }
}

__global__ void scan_kernel() {
    int s = 0;
#pragma unroll
    for (int e = 0; e < NE; e++) { g_base[e] = s; s += g_count[e]; }
}

__global__ void scatter_kernel() {
    int t = blockIdx.x * 256 + threadIdx.x;
    if (t >= TOK) return;
#pragma unroll
    for (int k = 0; k < 2; k++) {
        int e = g_topi[t*2+k];
        int pos = atomicAdd(&g_cursor[e], 1);
        int slot = g_base[e] + pos;
        g_perm[slot] = t;
        g_wt[slot]   = g_topw[t*2+k];
        g_slot_of[t*2+k] = slot;
    }
}

// ---------------- grouped GEMM: fp16 mma.sync, paired K16 chunks, 4 stages ----------------
// R15-proven pipeline/swizzle (32B rows, physical 16B half = h ^ ((row>>2)&1),
// one barrier per K32 pair, fp32-accumulator HMMA).
// NEW: tile M is pass-dependent: PASS1 = 128x128 (8 warps 4m x 2n),
// PASS2 = 64x128 (8 warps 2m x 4n) -> ~2x CTA parallelism for the wave-starved
// second GEMM (HD/128 = only 4 n-tiles).
template<int KDIM, int NDIM, bool PASS1>
__global__ __launch_bounds__(256, 2)
void moe_gemm_t(const float* __restrict__ bias) {
    constexpr int BM   = PASS1 ? 128 : 64;   // CTA m-tile
    constexpr int NT   = PASS1 ? 8 : 4;      // n8 tiles per warp
    constexpr int PLBA = BM * 32;            // A plane bytes per stage
    constexpr int PLBB = 4096;               // B plane bytes (128 rows x 32B)
    constexpr int STGB = PLBA + PLBB;

    __shared__ __align__(16) char smem[4*STGB];

    int e   = blockIdx.z;
    int cnt = g_count[e];
    int m0  = blockIdx.y * BM;
    if (m0 >= cnt) return;
    int n0   = blockIdx.x * 128;
    int base = g_base[e];

    int tid = threadIdx.x, wid = tid >> 5, lane = tid & 31;
    int wm = PASS1 ? (wid & 3) : (wid & 1);
    int wn = PASS1 ? (wid >> 2) : (wid >> 1);
    uint32_t smb = smaddr(smem);

    const __half* A_g = PASS1 ? gx16 : gact16;
    const __half* B_g = PASS1 ? gw1  : gw2;

    // loader: threads [0,BM) -> A row tid; [BM,BM+128) -> B row tid-BM; rest idle
    bool ldA = tid < BM;
    bool ldB = !ldA && tid < BM + 128;
    bool act = ldA || ldB;
    int  r   = ldA ? tid : (tid - BM);
    const char* src;
    if (ldA) {
        int mr = m0 + r; if (mr >= cnt) mr = cnt - 1;
        int ar = PASS1 ? g_perm[base + mr] : (base + mr);
        src = (const char*)(A_g + (size_t)ar * KDIM);
    } else {
        int br = ldB ? r : 0;
        src = (const char*)(B_g + ((size_t)e * NDIM + n0 + br) * KDIM);
    }
    int s = (r >> 2) & 1;
    uint32_t pb = ldA ? 0u : (uint32_t)PLBA;
    uint32_t d0 = pb + (uint32_t)(r*32 + s*16);
    uint32_t d1 = pb + (uint32_t)(r*32 + (s^1)*16);

    float acc[2][NT][4];
#pragma unroll
    for (int a = 0; a < 2; a++)
#pragma unroll
        for (int b = 0; b < NT; b++)
#pragma unroll
            for (int c = 0; c < 4; c++) acc[a][b][c] = 0.f;

    // ldmatrix lane addressing (fragment mapping proven R3..R15)
    const int a_r = lane & 15, ac = lane >> 4;
    const int b_n = ((lane >> 4) & 1) * 8 + (lane & 7);
    const int bc  = (lane >> 3) & 1;

    const int NCH = KDIM / 16;   // 32 or 128 (even)

    // prologue: chunks 0,1 into stages 0,1
    if (act) {
        cp16(smb + 0*STGB + d0, src);        cp16(smb + 0*STGB + d1, src + 16);
        cp16(smb + 1*STGB + d0, src + 32);   cp16(smb + 1*STGB + d1, src + 48);
    }
    CPC();

    for (int ci = 0; ci < NCH; ci += 2) {
        cpw<0>();
        __syncthreads();
        if (ci + 2 < NCH) {
            if (act) {
                uint32_t sgA = smb + ((ci + 2) & 3) * STGB;
                uint32_t sgB = smb + ((ci + 3) & 3) * STGB;
                uint32_t go  = (uint32_t)(ci + 2) * 32;
                cp16(sgA + d0, src + go);       cp16(sgA + d1, src + go + 16);
                cp16(sgB + d0, src + go + 32);  cp16(sgB + d1, src + go + 48);
            }
            CPC();
        }

#pragma unroll
        for (int j = 0; j < 2; j++) {
            uint32_t sb = smb + ((ci + j) & 3) * STGB;
            uint32_t ah[2][4];
#pragma unroll
            for (int mt = 0; mt < 2; mt++) {
                int row = wm*32 + mt*16 + a_r;
                uint32_t co = (uint32_t)((ac ^ ((row >> 2) & 1)) * 16);
                ldmx4(ah[mt], sb + row*32 + co);
            }
#pragma unroll
            for (int p4 = 0; p4 < NT/2; p4++) {
                int row = wn*(NT*8) + p4*16 + b_n;
                uint32_t co = (uint32_t)((bc ^ ((row >> 2) & 1)) * 16);
                uint32_t bh[4];
                ldmx4(bh, sb + PLBA + row*32 + co);
#pragma unroll
                for (int mt = 0; mt < 2; mt++) {
                    hmma(acc[mt][p4*2 + 0], ah[mt], &bh[0]);
                    hmma(acc[mt][p4*2 + 1], ah[mt], &bh[2]);
                }
            }
        }
    }

    // epilogue
    int rbase = wm*32 + (lane >> 2);
    int cbase = n0 + wn*(NT*8) + (lane & 3)*2;
#pragma unroll
    for (int mt = 0; mt < 2; mt++) {
#pragma unroll
        for (int sub = 0; sub < 2; sub++) {
            int m = m0 + rbase + mt*16 + sub*8;
            if (m >= cnt) continue;
            int slot = base + m;
            float wtv = PASS1 ? 1.f : g_wt[slot];
#pragma unroll
            for (int nt = 0; nt < NT; nt++) {
                int n = cbase + nt*8;
                float v0 = acc[mt][nt][sub*2+0] + __ldg(&bias[e*NDIM + n]);
                float v1 = acc[mt][nt][sub*2+1] + __ldg(&bias[e*NDIM + n + 1]);
                if (PASS1) {
                    v0 = v0 / (1.f + __expf(-v0));
                    v1 = v1 / (1.f + __expf(-v1));
                    uint32_t pk = (uint32_t)__half_as_ushort(__float2half_rn(v0))
                                | ((uint32_t)__half_as_ushort(__float2half_rn(v1)) << 16);
                    *(uint32_t*)(gact16 + (size_t)slot * NDIM + n) = pk;
                } else {
                    float2 o; o.x = v0 * wtv; o.y = v1 * wtv;
                    *(float2*)(gyy + (size_t)slot * NDIM + n) = o;
                }
            }
        }
    }
}

// ---------------- combine ----------------
__global__ void combine_kernel(float* __restrict__ out) {
    int idx = blockIdx.x * 256 + threadIdx.x;
    if (idx >= TOK * (HD/4)) return;
    int t  = idx / (HD/4);
    int h4 = idx % (HD/4);
    int s0 = g_slot_of[t*2+0];
    int s1 = g_slot_of[t*2+1];
    float4 a = *(const float4*)&gyy[(size_t)s0 * HD + h4*4];
    float4 b = *(const float4*)&gyy[(size_t)s1 * HD + h4*4];
    float4 o;
    o.x = a.x + b.x; o.y = a.y + b.y; o.z = a.z + b.z; o.w = a.w + b.w;
    *(float4*)&out[(size_t)t * HD + h4*4] = o;
}

// ---------------- launch ----------------
extern "C" void kernel_launch(void* const* d_in, const int* in_sizes, int n_in,
                              void* d_out, int out_size) {
    const float* x  = (const float*)d_in[0];
    const float* Wg = (const float*)d_in[1];
    const float* W1 = (const float*)d_in[2];  // [8][512][2048]
    const float* b1 = (const float*)d_in[3];
    const float* W2 = (const float*)d_in[4];  // [8][2048][512]
    const float* b2 = (const float*)d_in[5];
    float* out = (float*)d_out;

    init_kernel<<<1, 32>>>();
    w_transpose_kernel<HD, FD, true ><<<dim3(FD/32, HD/64, NE), dim3(32, 8)>>>(W1);
    w_transpose_kernel<FD, HD, false><<<dim3(HD/32, FD/64, NE), dim3(32, 8)>>>(W2);
    router_cvt_kernel<<<TOK/8, 256>>>(x, Wg);
    scan_kernel<<<1, 1>>>();
    scatter_kernel<<<TOK/256, 256>>>();

    // Pass A: 128x128 tiles — gather(fp16 x) @ W1T -> silu -> gact16
    moe_gemm_t<HD, FD, true><<<dim3(FD/128, 16, NE), 256>>>(b1);
    // Pass B: 64x128 tiles (2x CTA parallelism) — gact16 @ W2T -> *wt -> gyy
    moe_gemm_t<FD, HD, false><<<dim3(HD/128, 32, NE), 256>>>(b2);

    combine_kernel<<<(TOK*(HD/4) + 255)/256, 256>>>(out);
}